// round 8
// baseline (speedup 1.0000x reference)
#include <cuda_runtime.h>
#include <cstdint>

// ---------------- constants ----------------
#define B_   8
#define CIN  64
#define COUT 64
#define H_   96
#define W_   96
#define HW   (H_*W_)          // 9216
#define KK   9                // 3x3 taps
#define OFFC 18               // 2*KK offset channels

// ---------------- f32x2 helpers (Blackwell packed fp32) ----------------
__device__ __forceinline__ unsigned long long fma2(unsigned long long a,
                                                   unsigned long long b,
                                                   unsigned long long c) {
    unsigned long long d;
    asm("fma.rn.f32x2 %0, %1, %2, %3;" : "=l"(d) : "l"(a), "l"(b), "l"(c));
    return d;
}
__device__ __forceinline__ unsigned long long pack2(float lo, float hi) {
    unsigned long long d;
    asm("mov.b64 %0, {%1, %2};" : "=l"(d) : "f"(lo), "f"(hi));
    return d;
}
__device__ __forceinline__ float2 unpack2(unsigned long long v) {
    float2 r;
    asm("mov.b64 {%0, %1}, %2;" : "=f"(r.x), "=f"(r.y) : "l"(v));
    return r;
}

// ---------------- scratch ----------------
__device__ float g_xT[B_ * HW * CIN];       // NHWC transposed x
__device__ float g_off[B_ * OFFC * HW];     // offset field
__device__ float g_wT[KK * CIN * COUT];     // weight as [kk][c][oc]

// ============================================================
// Kernel 1: NCHW -> NHWC transpose of x
// ============================================================
__global__ __launch_bounds__(256) void transpose_x_kernel(const float* __restrict__ x)
{
    __shared__ float tile[32][33];
    int b   = blockIdx.z;
    int hw0 = blockIdx.x * 32;
    int c0  = blockIdx.y * 32;
    int tx = threadIdx.x, ty = threadIdx.y;

    const float* src = x + (size_t)b * CIN * HW;
#pragma unroll
    for (int i = 0; i < 32; i += 8)
        tile[ty + i][tx] = src[(size_t)(c0 + ty + i) * HW + hw0 + tx];
    __syncthreads();
    float* dst = g_xT + (size_t)b * HW * CIN;
#pragma unroll
    for (int i = 0; i < 32; i += 8)
        dst[(size_t)(hw0 + ty + i) * CIN + c0 + tx] = tile[tx][ty + i];
}

// ============================================================
// Kernel 2: weight (oc, c, kk) -> wT[kk][c][oc]
// ============================================================
__global__ __launch_bounds__(256) void transpose_w_kernel(const float* __restrict__ w)
{
    int idx = blockIdx.x * 256 + threadIdx.x;
    if (idx < COUT * CIN * KK) {
        int kk = idx % KK;
        int c  = (idx / KK) % CIN;
        int oc = idx / (KK * CIN);
        g_wT[(kk * CIN + c) * COUT + oc] = w[idx];
    }
}

// ============================================================
// Kernel 3: offset conv with f32x2
// ============================================================
__global__ __launch_bounds__(256) void offset_conv_kernel(
    const float* __restrict__ x,
    const float* __restrict__ off_w,
    const float* __restrict__ off_b)
{
    __shared__ float wS[576][20];

    int tid = threadIdx.x;
    for (int i = tid; i < OFFC * 576; i += 256) {
        int o = i / 576;
        int r = i % 576;
        wS[r][o] = off_w[i];
    }
    for (int r = tid; r < 576; r += 256) { wS[r][18] = 0.f; wS[r][19] = 0.f; }
    __syncthreads();

    int b   = blockIdx.z;
    int wo  = blockIdx.x * 32 + (tid & 31);
    int ho  = blockIdx.y * 8  + (tid >> 5);

    unsigned long long acc2[9];
#pragma unroll
    for (int j = 0; j < 9; ++j) acc2[j] = 0ull;

    const float* xb = x + (size_t)b * CIN * HW;

    for (int c = 0; c < CIN; ++c) {
        const float* xc = xb + (size_t)c * HW;
#pragma unroll
        for (int kh = 0; kh < 3; ++kh) {
            int y = ho + kh - 1;
            bool vy = ((unsigned)y < (unsigned)H_);
#pragma unroll
            for (int kw = 0; kw < 3; ++kw) {
                int xx = wo + kw - 1;
                float xv = 0.f;
                if (vy && (unsigned)xx < (unsigned)W_)
                    xv = __ldg(xc + y * W_ + xx);
                unsigned long long xp = pack2(xv, xv);
                const float* wr = &wS[c * 9 + kh * 3 + kw][0];
                ulonglong2 wA = *(const ulonglong2*)(wr + 0);
                ulonglong2 wB = *(const ulonglong2*)(wr + 4);
                ulonglong2 wC = *(const ulonglong2*)(wr + 8);
                ulonglong2 wD = *(const ulonglong2*)(wr + 12);
                unsigned long long wE = *(const unsigned long long*)(wr + 16);
                acc2[0] = fma2(xp, wA.x, acc2[0]);
                acc2[1] = fma2(xp, wA.y, acc2[1]);
                acc2[2] = fma2(xp, wB.x, acc2[2]);
                acc2[3] = fma2(xp, wB.y, acc2[3]);
                acc2[4] = fma2(xp, wC.x, acc2[4]);
                acc2[5] = fma2(xp, wC.y, acc2[5]);
                acc2[6] = fma2(xp, wD.x, acc2[6]);
                acc2[7] = fma2(xp, wD.y, acc2[7]);
                acc2[8] = fma2(xp, wE,   acc2[8]);
            }
        }
    }

#pragma unroll
    for (int j = 0; j < 9; ++j) {
        float2 f = unpack2(acc2[j]);
        g_off[((size_t)(b * OFFC + 2 * j)     * H_ + ho) * W_ + wo] = f.x + __ldg(&off_b[2 * j]);
        g_off[((size_t)(b * OFFC + 2 * j + 1) * H_ + ho) * W_ + wo] = f.y + __ldg(&off_b[2 * j + 1]);
    }
}

// ============================================================
// Kernel 4: deformable conv main (f32x2 GEMM, 64-pix tile)
// block tile: 64 pixels (4 ho x 16 wo) x 64 oc, 256 threads
// grid (6, 24, 8) = 1152 blocks
// smem static: sS[64 c][68 pix-padded] + wSh[64][64] + sOff[18][64]  (~38 KB)
// sampling: warp = channel-group of 8, lane = pixel-pair of 2
//   gather: 2x LDG.128 per corner; STS: contiguous float2 rows (conflict-free)
// GEMM: 4 pix x 4 oc per thread; per c: 2x LDS.128 + 8x fma.rn.f32x2
// ============================================================
__global__ __launch_bounds__(256) void deform_kernel(
    const float* __restrict__ bias,
    float* __restrict__ out)
{
    __shared__ float sS[64 * 68];      // [c][pix], 68-padded rows
    __shared__ float wSh[64 * 64];     // [c][oc]
    __shared__ float sOff[OFFC * 64];  // [o][pix]

    int tid = threadIdx.x;
    int b   = blockIdx.z;
    int wo0 = blockIdx.x * 16;
    int ho0 = blockIdx.y * 4;

    // sampling mapping: warp = channel group (8 ch), lane = pixel pair
    int pg = tid & 31;          // pixel pair index: pixels {2pg, 2pg+1}
    int cg = tid >> 5;          // 8 channel groups of 8
    int c0 = cg * 8;

    // GEMM mapping
    int tx  = tid & 15;
    int ty  = tid >> 4;
    int oc0 = tx * 4;
    int p0  = ty * 4;

    // ---- stage offsets (18 x 64) ----
    const float* offb = g_off + (size_t)b * OFFC * HW;
    for (int i = tid; i < OFFC * 64; i += 256) {
        int o = i >> 6;
        int p = i & 63;
        sOff[o * 64 + p] = offb[(size_t)o * HW + (ho0 + (p >> 4)) * W_ + wo0 + (p & 15)];
    }

    unsigned long long acc[2][4];   // [pixel-pair q][oc j]
#pragma unroll
    for (int i = 0; i < 2; ++i)
#pragma unroll
        for (int j = 0; j < 4; ++j) acc[i][j] = 0ull;

    const float* xTb = g_xT + (size_t)b * HW * CIN;

    for (int kk = 0; kk < KK; ++kk) {
        __syncthreads();   // offsets ready (iter 0) / previous GEMM done reading

        // ---- stage weight chunk wT[kk]: 4096 floats ----
        {
            const float4* src = (const float4*)(g_wT + kk * CIN * COUT);
            float4* dst = (float4*)wSh;
#pragma unroll
            for (int r = 0; r < 4; ++r)
                dst[tid + r * 256] = src[tid + r * 256];
        }

        // ---- bilinear sampling: 2 pixels x 8 channels per thread ----
        {
            int ky = kk / 3 - 1;
            int kx = kk % 3 - 1;
            unsigned long long vp[4][2];   // [channel-pair m][pixel q]
#pragma unroll
            for (int m = 0; m < 4; ++m) { vp[m][0] = 0ull; vp[m][1] = 0ull; }

#pragma unroll
            for (int q = 0; q < 2; ++q) {
                int pix  = pg * 2 + q;
                int ho_s = ho0 + (pix >> 4);
                int wo_s = wo0 + (pix & 15);
                float offy = sOff[(2 * kk) * 64 + pix];
                float offx = sOff[(2 * kk + 1) * 64 + pix];
                float sy = (float)(ho_s + 1 + ky) + offy;
                float sx = (float)(wo_s + 1 + kx) + offx;
                float y0f = floorf(sy), x0f = floorf(sx);
                float wy1 = sy - y0f, wx1 = sx - x0f;
                float wy0 = 1.f - wy1, wx0 = 1.f - wx1;
                int y0 = (int)y0f, x0 = (int)x0f;
                int y1 = y0 + 1,   x1 = x0 + 1;
                bool vy0 = ((unsigned)y0 < (unsigned)H_);
                bool vy1 = ((unsigned)y1 < (unsigned)H_);
                bool vx0 = ((unsigned)x0 < (unsigned)W_);
                bool vx1 = ((unsigned)x1 < (unsigned)W_);

#define GATHER2(YI, XI, WW, VALID)                                                     \
                if (VALID) {                                                           \
                    const ulonglong2* p =                                              \
                        (const ulonglong2*)(xTb + ((size_t)((YI) * W_ + (XI))) * CIN + c0); \
                    ulonglong2 a = p[0], bb = p[1];                                    \
                    unsigned long long wp = pack2((WW), (WW));                         \
                    vp[0][q] = fma2(a.x,  wp, vp[0][q]);                               \
                    vp[1][q] = fma2(a.y,  wp, vp[1][q]);                               \
                    vp[2][q] = fma2(bb.x, wp, vp[2][q]);                               \
                    vp[3][q] = fma2(bb.y, wp, vp[3][q]);                               \
                }
                GATHER2(y0, x0, wy0 * wx0, vy0 && vx0)
                GATHER2(y0, x1, wy0 * wx1, vy0 && vx1)
                GATHER2(y1, x0, wy1 * wx0, vy1 && vx0)
                GATHER2(y1, x1, wy1 * wx1, vy1 && vx1)
#undef GATHER2
            }

            // store [c][pix]: per channel row, 32 lanes write 128 contiguous B
#pragma unroll
            for (int m = 0; m < 4; ++m) {
                float2 f0 = unpack2(vp[m][0]);   // pixel 2pg   : ch c0+2m, c0+2m+1
                float2 f1 = unpack2(vp[m][1]);   // pixel 2pg+1
                *(float2*)&sS[(c0 + 2 * m)     * 68 + pg * 2] = make_float2(f0.x, f1.x);
                *(float2*)&sS[(c0 + 2 * m + 1) * 68 + pg * 2] = make_float2(f0.y, f1.y);
            }
        }

        __syncthreads();

        // ---- f32x2 GEMM: 4 pix x 4 oc per thread; 2 LDS.128 + 8 FMA2 per c ----
#pragma unroll 4
        for (int c = 0; c < CIN; ++c) {
            ulonglong2 sp = *(const ulonglong2*)&sS[c * 68 + p0];   // pix pairs 0,1
            float4 wv = *(const float4*)&wSh[c * 64 + oc0];
            unsigned long long w0 = pack2(wv.x, wv.x);
            unsigned long long w1 = pack2(wv.y, wv.y);
            unsigned long long w2 = pack2(wv.z, wv.z);
            unsigned long long w3 = pack2(wv.w, wv.w);
            acc[0][0] = fma2(sp.x, w0, acc[0][0]);
            acc[0][1] = fma2(sp.x, w1, acc[0][1]);
            acc[0][2] = fma2(sp.x, w2, acc[0][2]);
            acc[0][3] = fma2(sp.x, w3, acc[0][3]);
            acc[1][0] = fma2(sp.y, w0, acc[1][0]);
            acc[1][1] = fma2(sp.y, w1, acc[1][1]);
            acc[1][2] = fma2(sp.y, w2, acc[1][2]);
            acc[1][3] = fma2(sp.y, w3, acc[1][3]);
        }
    }

    // ---- epilogue: transpose via smem [oc][pix], coalesced NCHW stores ----
    __syncthreads();
#pragma unroll
    for (int q = 0; q < 2; ++q)
#pragma unroll
        for (int j = 0; j < 4; ++j)
            *(unsigned long long*)&sS[(oc0 + j) * 68 + p0 + 2 * q] = acc[q][j];
    __syncthreads();

    float* outb = out + (size_t)b * COUT * HW;
#pragma unroll
    for (int r = 0; r < 16; ++r) {
        int idx = r * 256 + tid;
        int oc  = idx >> 6;
        int pix = idx & 63;
        int ho  = ho0 + (pix >> 4);
        int wo  = wo0 + (pix & 15);
        outb[(size_t)oc * HW + ho * W_ + wo] = sS[oc * 68 + pix] + __ldg(&bias[oc]);
    }
}

// ============================================================
// launch
// ============================================================
extern "C" void kernel_launch(void* const* d_in, const int* in_sizes, int n_in,
                              void* d_out, int out_size)
{
    const float* x      = (const float*)d_in[0];
    const float* weight = (const float*)d_in[1];
    const float* bias   = (const float*)d_in[2];
    const float* off_w  = (const float*)d_in[3];
    const float* off_b  = (const float*)d_in[4];
    float* out = (float*)d_out;

    // 1) layout transforms
    {
        dim3 grid(HW / 32, CIN / 32, B_);
        dim3 block(32, 8);
        transpose_x_kernel<<<grid, block>>>(x);
    }
    {
        int n = COUT * CIN * KK;
        transpose_w_kernel<<<(n + 255) / 256, 256>>>(weight);
    }
    // 2) offset conv
    {
        dim3 grid(W_ / 32, H_ / 8, B_);
        offset_conv_kernel<<<grid, 256>>>(x, off_w, off_b);
    }
    // 3) deformable conv
    {
        dim3 grid(W_ / 16, H_ / 4, B_);
        deform_kernel<<<grid, 256>>>(bias, out);
    }
}

// round 9
// speedup vs baseline: 1.4336x; 1.4336x over previous
#include <cuda_runtime.h>
#include <cstdint>

// ---------------- constants ----------------
#define B_   8
#define CIN  64
#define COUT 64
#define H_   96
#define W_   96
#define HW   (H_*W_)          // 9216
#define KK   9                // 3x3 taps
#define OFFC 18               // 2*KK offset channels
#define PIT  132              // sS pixel pitch (16B-aligned rows, 4-way STS conflict)

// ---------------- f32x2 helpers (Blackwell packed fp32) ----------------
__device__ __forceinline__ unsigned long long fma2(unsigned long long a,
                                                   unsigned long long b,
                                                   unsigned long long c) {
    unsigned long long d;
    asm("fma.rn.f32x2 %0, %1, %2, %3;" : "=l"(d) : "l"(a), "l"(b), "l"(c));
    return d;
}
__device__ __forceinline__ unsigned long long pack2(float lo, float hi) {
    unsigned long long d;
    asm("mov.b64 %0, {%1, %2};" : "=l"(d) : "f"(lo), "f"(hi));
    return d;
}
__device__ __forceinline__ float2 unpack2(unsigned long long v) {
    float2 r;
    asm("mov.b64 {%0, %1}, %2;" : "=f"(r.x), "=f"(r.y) : "l"(v));
    return r;
}

// ---------------- scratch ----------------
__device__ float g_xT[B_ * HW * CIN];       // NHWC transposed x
__device__ float g_off[B_ * OFFC * HW];     // offset field
__device__ float g_wT[KK * CIN * COUT];     // weight as [kk][c][oc]

// ============================================================
// Kernel 1: NCHW -> NHWC transpose of x
// ============================================================
__global__ __launch_bounds__(256) void transpose_x_kernel(const float* __restrict__ x)
{
    __shared__ float tile[32][33];
    int b   = blockIdx.z;
    int hw0 = blockIdx.x * 32;
    int c0  = blockIdx.y * 32;
    int tx = threadIdx.x, ty = threadIdx.y;

    const float* src = x + (size_t)b * CIN * HW;
#pragma unroll
    for (int i = 0; i < 32; i += 8)
        tile[ty + i][tx] = src[(size_t)(c0 + ty + i) * HW + hw0 + tx];
    __syncthreads();
    float* dst = g_xT + (size_t)b * HW * CIN;
#pragma unroll
    for (int i = 0; i < 32; i += 8)
        dst[(size_t)(hw0 + ty + i) * CIN + c0 + tx] = tile[tx][ty + i];
}

// ============================================================
// Kernel 2: weight (oc, c, kk) -> wT[kk][c][oc]
// ============================================================
__global__ __launch_bounds__(256) void transpose_w_kernel(const float* __restrict__ w)
{
    int idx = blockIdx.x * 256 + threadIdx.x;
    if (idx < COUT * CIN * KK) {
        int kk = idx % KK;
        int c  = (idx / KK) % CIN;
        int oc = idx / (KK * CIN);
        g_wT[(kk * CIN + c) * COUT + oc] = w[idx];
    }
}

// ============================================================
// Kernel 3: offset conv with f32x2
// ============================================================
__global__ __launch_bounds__(256) void offset_conv_kernel(
    const float* __restrict__ x,
    const float* __restrict__ off_w,
    const float* __restrict__ off_b)
{
    __shared__ float wS[576][20];

    int tid = threadIdx.x;
    for (int i = tid; i < OFFC * 576; i += 256) {
        int o = i / 576;
        int r = i % 576;
        wS[r][o] = off_w[i];
    }
    for (int r = tid; r < 576; r += 256) { wS[r][18] = 0.f; wS[r][19] = 0.f; }
    __syncthreads();

    int b   = blockIdx.z;
    int wo  = blockIdx.x * 32 + (tid & 31);
    int ho  = blockIdx.y * 8  + (tid >> 5);

    unsigned long long acc2[9];
#pragma unroll
    for (int j = 0; j < 9; ++j) acc2[j] = 0ull;

    const float* xb = x + (size_t)b * CIN * HW;

    for (int c = 0; c < CIN; ++c) {
        const float* xc = xb + (size_t)c * HW;
#pragma unroll
        for (int kh = 0; kh < 3; ++kh) {
            int y = ho + kh - 1;
            bool vy = ((unsigned)y < (unsigned)H_);
#pragma unroll
            for (int kw = 0; kw < 3; ++kw) {
                int xx = wo + kw - 1;
                float xv = 0.f;
                if (vy && (unsigned)xx < (unsigned)W_)
                    xv = __ldg(xc + y * W_ + xx);
                unsigned long long xp = pack2(xv, xv);
                const float* wr = &wS[c * 9 + kh * 3 + kw][0];
                ulonglong2 wA = *(const ulonglong2*)(wr + 0);
                ulonglong2 wB = *(const ulonglong2*)(wr + 4);
                ulonglong2 wC = *(const ulonglong2*)(wr + 8);
                ulonglong2 wD = *(const ulonglong2*)(wr + 12);
                unsigned long long wE = *(const unsigned long long*)(wr + 16);
                acc2[0] = fma2(xp, wA.x, acc2[0]);
                acc2[1] = fma2(xp, wA.y, acc2[1]);
                acc2[2] = fma2(xp, wB.x, acc2[2]);
                acc2[3] = fma2(xp, wB.y, acc2[3]);
                acc2[4] = fma2(xp, wC.x, acc2[4]);
                acc2[5] = fma2(xp, wC.y, acc2[5]);
                acc2[6] = fma2(xp, wD.x, acc2[6]);
                acc2[7] = fma2(xp, wD.y, acc2[7]);
                acc2[8] = fma2(xp, wE,   acc2[8]);
            }
        }
    }

#pragma unroll
    for (int j = 0; j < 9; ++j) {
        float2 f = unpack2(acc2[j]);
        g_off[((size_t)(b * OFFC + 2 * j)     * H_ + ho) * W_ + wo] = f.x + __ldg(&off_b[2 * j]);
        g_off[((size_t)(b * OFFC + 2 * j + 1) * H_ + ho) * W_ + wo] = f.y + __ldg(&off_b[2 * j + 1]);
    }
}

// ============================================================
// Kernel 4: deformable conv main — wavefront-minimized
// block: 128 pixels (8 ho x 16 wo) x 64 oc, 256 threads, grid (6,12,8)=576
// smem (dynamic 59.4KB): sS[64][PIT] + wSh[64][64] + sOff[18][128]
// sampling: warp w owns pixels 16w..16w+15; per corner lane l loads channels
//   l and l+32 (two LDG.32 = two FULL 128B lines = 2 wavefronts, 100% util)
// GEMM: thread = 8 pix x 4 oc, f32x2; warp = 8 oc-groups x 4 pix-groups so
//   weight LDS.128 spans 128B contiguous (1 wf), pixel LDS.128s span 128B (2 wf)
// ============================================================
__global__ __launch_bounds__(256, 3) void deform_kernel(
    const float* __restrict__ bias,
    float* __restrict__ out)
{
    extern __shared__ float smem[];
    float* sS   = smem;                      // 64*132 = 8448
    float* wSh  = smem + 64 * PIT;           // 4096
    float* sOff = smem + 64 * PIT + 64 * 64; // 2304

    int tid  = threadIdx.x;
    int warp = tid >> 5;
    int lane = tid & 31;
    int b    = blockIdx.z;
    int wo0  = blockIdx.x * 16;
    int ho0  = blockIdx.y * 8;

    // GEMM mapping: warp = 8 oc-groups (lane&7) x 4 pix-groups (lane>>3)
    int ocg  = (lane & 7) | ((warp & 1) << 3);   // 0..15
    int pixg = (lane >> 3) | ((warp >> 1) << 2); // 0..15
    int oc0  = ocg * 4;
    int p0   = pixg * 8;

    // ---- stage offsets (18 x 128) ----
    const float* offb = g_off + (size_t)b * OFFC * HW;
    for (int i = tid; i < OFFC * 128; i += 256) {
        int o = i >> 7;
        int p = i & 127;
        sOff[o * 128 + p] = offb[(size_t)o * HW + (ho0 + (p >> 4)) * W_ + wo0 + (p & 15)];
    }

    unsigned long long acc[4][4];   // [pixel-pair q: pixels p0+2q,p0+2q+1][oc j]
#pragma unroll
    for (int i = 0; i < 4; ++i)
#pragma unroll
        for (int j = 0; j < 4; ++j) acc[i][j] = 0ull;

    const float* xTb = g_xT + (size_t)b * HW * CIN;

    for (int kk = 0; kk < KK; ++kk) {
        __syncthreads();   // offsets ready (iter 0) / prev GEMM done reading

        // ---- stage weight chunk wT[kk]: 4096 floats ----
        {
            const float4* src = (const float4*)(g_wT + kk * CIN * COUT);
            float4* dst = (float4*)wSh;
#pragma unroll
            for (int r = 0; r < 4; ++r)
                dst[tid + r * 256] = src[tid + r * 256];
        }

        // ---- sampling: warp owns 16 pixels; lane = channels (l, l+32) ----
        {
            int ky = kk / 3 - 1;
            int kx = kk % 3 - 1;
#pragma unroll 2
            for (int t = 0; t < 16; ++t) {
                int pix  = warp * 16 + t;
                int ho_s = ho0 + (pix >> 4);
                int wo_s = wo0 + (pix & 15);
                float offy = sOff[(2 * kk) * 128 + pix];
                float offx = sOff[(2 * kk + 1) * 128 + pix];
                float sy = (float)(ho_s + 1 + ky) + offy;
                float sx = (float)(wo_s + 1 + kx) + offx;
                float y0f = floorf(sy), x0f = floorf(sx);
                float wy1 = sy - y0f, wx1 = sx - x0f;
                float wy0 = 1.f - wy1, wx0 = 1.f - wx1;
                int y0 = (int)y0f, x0 = (int)x0f;
                int y1 = y0 + 1,   x1 = x0 + 1;
                bool vy0 = ((unsigned)y0 < (unsigned)H_);
                bool vy1 = ((unsigned)y1 < (unsigned)H_);
                bool vx0 = ((unsigned)x0 < (unsigned)W_);
                bool vx1 = ((unsigned)x1 < (unsigned)W_);

                float aLo = 0.f, aHi = 0.f;
#define GC(YI, XI, WW, V)                                                   \
                if (V) {                                                    \
                    const float* pb_ = xTb + (size_t)((YI) * W_ + (XI)) * CIN; \
                    float ww = (WW);                                        \
                    aLo = fmaf(ww, __ldg(pb_ + lane),      aLo);            \
                    aHi = fmaf(ww, __ldg(pb_ + lane + 32), aHi);            \
                }
                GC(y0, x0, wy0 * wx0, vy0 && vx0)
                GC(y0, x1, wy0 * wx1, vy0 && vx1)
                GC(y1, x0, wy1 * wx0, vy1 && vx0)
                GC(y1, x1, wy1 * wx1, vy1 && vx1)
#undef GC
                sS[lane * PIT + pix]        = aLo;
                sS[(lane + 32) * PIT + pix] = aHi;
            }
        }

        __syncthreads();

        // ---- f32x2 GEMM: 8 pix x 4 oc per thread ----
#pragma unroll 4
        for (int c = 0; c < CIN; ++c) {
            ulonglong2 spA = *(const ulonglong2*)&sS[c * PIT + p0];      // pix pairs 0,1
            ulonglong2 spB = *(const ulonglong2*)&sS[c * PIT + p0 + 4];  // pix pairs 2,3
            float4 wv = *(const float4*)&wSh[c * 64 + oc0];
            unsigned long long w0 = pack2(wv.x, wv.x);
            unsigned long long w1 = pack2(wv.y, wv.y);
            unsigned long long w2 = pack2(wv.z, wv.z);
            unsigned long long w3 = pack2(wv.w, wv.w);
            acc[0][0] = fma2(spA.x, w0, acc[0][0]);
            acc[0][1] = fma2(spA.x, w1, acc[0][1]);
            acc[0][2] = fma2(spA.x, w2, acc[0][2]);
            acc[0][3] = fma2(spA.x, w3, acc[0][3]);
            acc[1][0] = fma2(spA.y, w0, acc[1][0]);
            acc[1][1] = fma2(spA.y, w1, acc[1][1]);
            acc[1][2] = fma2(spA.y, w2, acc[1][2]);
            acc[1][3] = fma2(spA.y, w3, acc[1][3]);
            acc[2][0] = fma2(spB.x, w0, acc[2][0]);
            acc[2][1] = fma2(spB.x, w1, acc[2][1]);
            acc[2][2] = fma2(spB.x, w2, acc[2][2]);
            acc[2][3] = fma2(spB.x, w3, acc[2][3]);
            acc[3][0] = fma2(spB.y, w0, acc[3][0]);
            acc[3][1] = fma2(spB.y, w1, acc[3][1]);
            acc[3][2] = fma2(spB.y, w2, acc[3][2]);
            acc[3][3] = fma2(spB.y, w3, acc[3][3]);
        }
    }

    // ---- epilogue: write acc to sS as [oc][pix], coalesced NCHW stores ----
    __syncthreads();
#pragma unroll
    for (int q = 0; q < 4; ++q)
#pragma unroll
        for (int j = 0; j < 4; ++j)
            *(unsigned long long*)&sS[(oc0 + j) * PIT + p0 + 2 * q] = acc[q][j];
    __syncthreads();

    float* outb = out + (size_t)b * COUT * HW;
#pragma unroll
    for (int r = 0; r < 32; ++r) {
        int idx = r * 256 + tid;
        int oc  = idx >> 7;
        int pix = idx & 127;
        int ho  = ho0 + (pix >> 4);
        int wo  = wo0 + (pix & 15);
        outb[(size_t)oc * HW + ho * W_ + wo] = sS[oc * PIT + pix] + __ldg(&bias[oc]);
    }
}

// ============================================================
// launch
// ============================================================
extern "C" void kernel_launch(void* const* d_in, const int* in_sizes, int n_in,
                              void* d_out, int out_size)
{
    const float* x      = (const float*)d_in[0];
    const float* weight = (const float*)d_in[1];
    const float* bias   = (const float*)d_in[2];
    const float* off_w  = (const float*)d_in[3];
    const float* off_b  = (const float*)d_in[4];
    float* out = (float*)d_out;

    const int deform_smem = (64 * PIT + 64 * 64 + OFFC * 128) * 4;   // 59392 B
    cudaFuncSetAttribute(deform_kernel,
                         cudaFuncAttributeMaxDynamicSharedMemorySize, deform_smem);

    // 1) layout transforms
    {
        dim3 grid(HW / 32, CIN / 32, B_);
        dim3 block(32, 8);
        transpose_x_kernel<<<grid, block>>>(x);
    }
    {
        int n = COUT * CIN * KK;
        transpose_w_kernel<<<(n + 255) / 256, 256>>>(weight);
    }
    // 2) offset conv
    {
        dim3 grid(W_ / 32, H_ / 8, B_);
        offset_conv_kernel<<<grid, 256>>>(x, off_w, off_b);
    }
    // 3) deformable conv
    {
        dim3 grid(W_ / 16, H_ / 8, B_);
        deform_kernel<<<grid, 256, deform_smem>>>(bias, out);
    }
}